// round 8
// baseline (speedup 1.0000x reference)
#include <cuda_runtime.h>

#define BN 256
#define TN 512
#define CN 128
#define FN 128
#define NB 32

typedef unsigned long long ull;

__device__ float g_scratch[(size_t)BN * TN * FN];   // 64 MB scratch

__device__ __forceinline__ ull pk2(float lo, float hi) {
    ull r; asm("mov.b64 %0, {%1, %2};" : "=l"(r) : "f"(lo), "f"(hi)); return r;
}
__device__ __forceinline__ void upk2(ull v, float& lo, float& hi) {
    asm("mov.b64 {%0, %1}, %2;" : "=f"(lo), "=f"(hi) : "l"(v));
}
__device__ __forceinline__ ull fma2(ull a, ull b, ull c) {
    ull d; asm("fma.rn.f32x2 %0, %1, %2, %3;" : "=l"(d) : "l"(a), "l"(b), "l"(c)); return d;
}
__device__ __forceinline__ float wsum(float v) {
    #pragma unroll
    for (int o = 16; o; o >>= 1) v += __shfl_xor_sync(0xffffffffu, v, o);
    return v;
}

// ============================================================
// Conv1D: writes y to BOTH d_out and scratch
// ============================================================
__global__ __launch_bounds__(256) void conv_kernel(
    const float* __restrict__ x, const float* __restrict__ W,
    const float* __restrict__ bias, float* __restrict__ y)
{
    __shared__ float Xs[64][33];
    __shared__ float Ws[32][128];

    const int b = blockIdx.y, t0 = blockIdx.x * 64, tid = threadIdx.x;
    const int lane = tid & 31, warp = tid >> 5;
    const int cbase = lane * 4, rbase = warp * 8;

    ull acc2[8][2];
    #pragma unroll
    for (int i = 0; i < 8; i++) { acc2[i][0] = 0ull; acc2[i][1] = 0ull; }

    for (int k = 0; k < 3; k++) {
        for (int c0 = 0; c0 < CN; c0 += 32) {
            #pragma unroll
            for (int q = 0; q < 16; q++) {
                int e = tid + 256 * q, f = e & 127, cc = e >> 7;
                Ws[cc][f] = W[((size_t)(k * CN + c0 + cc)) * FN + f];
            }
            #pragma unroll
            for (int q = 0; q < 8; q++) {
                int e = tid + 256 * q, cc = e & 31, r = e >> 5;
                int t = t0 + r + k - 1;
                float v = 0.f;
                if (t >= 0 && t < TN) v = x[((size_t)b * TN + t) * CN + c0 + cc];
                Xs[r][cc] = v;
            }
            __syncthreads();
            #pragma unroll
            for (int cc = 0; cc < 32; cc++) {
                const ull* wp = (const ull*)&Ws[cc][cbase];
                ull w01 = wp[0], w23 = wp[1];
                #pragma unroll
                for (int i = 0; i < 8; i++) {
                    float xv = Xs[rbase + i][cc];
                    ull xx = pk2(xv, xv);
                    acc2[i][0] = fma2(xx, w01, acc2[i][0]);
                    acc2[i][1] = fma2(xx, w23, acc2[i][1]);
                }
            }
            __syncthreads();
        }
    }
    float b0 = bias[cbase], b1 = bias[cbase+1], b2 = bias[cbase+2], b3 = bias[cbase+3];
    #pragma unroll
    for (int i = 0; i < 8; i++) {
        int t = t0 + rbase + i;
        float4 o; float lo, hi;
        upk2(acc2[i][0], lo, hi); o.x = lo + b0; o.y = hi + b1;
        upk2(acc2[i][1], lo, hi); o.z = lo + b2; o.w = hi + b3;
        size_t off = ((size_t)b * TN + t) * FN + cbase;
        *(float4*)&y[off] = o;
        *(float4*)&g_scratch[off] = o;
    }
}

// ============================================================
// geqrf (blocked WY, trailing-update only) + R^{-1}, one CTA per matrix.
// Leaves dense R^{-1} (zeros below diag) in scratch rows 0..127.
// ============================================================
#define VP(t,i)   Vp[(t) * 33 + (i)]
#define W2STRIDE  120

template<int WT>
__device__ void block_apply(float* __restrict__ G, int o, int colbase,
                            const float* __restrict__ Vp, const float* __restrict__ Tp,
                            float* __restrict__ Wm, float* __restrict__ Wm2, int tid)
{
    const int lane = tid & 31, w = tid >> 5;
    constexpr int NU = WT / 32;
    constexpr int HW = WT / 2;
    constexpr int TU = 32 * HW;
    ull* Gs = (ull*)Wm2;

    // GEMM1: Wm[i][c] = sum_t V[t][i]*G[t][colbase+c]
    ull acc[NU];
    #pragma unroll
    for (int k = 0; k < NU; k++) acc[k] = 0ull;
    const int ntiles = (TN - o) >> 5;
    for (int tile = 0; tile < ntiles; tile++) {
        const int t0 = o + (tile << 5);
        #pragma unroll
        for (int u = tid; u < TU; u += 512) {
            int r = u / HW, c = u - r * HW;
            Gs[u] = *(const ull*)(G + (size_t)(t0 + r) * FN + colbase + 2 * c);
        }
        __syncthreads();
        #pragma unroll
        for (int r = 0; r < 32; r++) {
            float v = VP(t0 + r, lane);
            ull vv = pk2(v, v);
            const ull* g = Gs + r * HW + w * NU;
            #pragma unroll
            for (int k = 0; k < NU; k++) acc[k] = fma2(vv, g[k], acc[k]);
        }
        __syncthreads();
    }
    {
        ull* wout = (ull*)(Wm + lane * 96) + w * NU;
        #pragma unroll
        for (int k = 0; k < NU; k++) wout[k] = acc[k];
    }
    __syncthreads();

    // Tapply: Wm2 = -(T^T * Wm), group-10 padded
    {
        constexpr int NCG = WT / 8;
        for (int pos = tid; pos < 32 * NCG * 4; pos += 512) {
            int i = pos / (NCG * 4);
            int rem = pos - i * (NCG * 4);
            int cg = rem >> 2, k = rem & 3;
            int c = cg * 8 + 2 * k;
            ull a = 0ull;
            #pragma unroll
            for (int j = 0; j < 32; j++) {
                float tv = Tp[j * 33 + i];
                a = fma2(pk2(-tv, -tv), *(const ull*)(Wm + j * 96 + c), a);
            }
            *(ull*)(Wm2 + i * W2STRIDE + cg * 10 + 2 * k) = a;
        }
    }
    __syncthreads();

    // GEMM2: G += V * Wm2
    {
        constexpr int NCG = WT / 8;
        const int npos = ((TN - o) >> 2) * NCG;
        for (int pos = tid; pos < npos; pos += 512) {
            int tg = pos / NCG, cg = pos - tg * NCG;
            int t0 = o + (tg << 2);
            float* gp = G + (size_t)t0 * FN + colbase + cg * 8;
            ull a[4][4];
            #pragma unroll
            for (int r = 0; r < 4; r++) {
                ulonglong2 q0 = ((const ulonglong2*)(gp + r * FN))[0];
                ulonglong2 q1 = ((const ulonglong2*)(gp + r * FN))[1];
                a[r][0] = q0.x; a[r][1] = q0.y; a[r][2] = q1.x; a[r][3] = q1.y;
            }
            const float* vr0 = Vp + (size_t)t0 * 33;
            const float* vr1 = vr0 + 33;
            const float* vr2 = vr1 + 33;
            const float* vr3 = vr2 + 33;
            const float* w2base = Wm2 + cg * 10;
            #pragma unroll 4
            for (int i = 0; i < 32; i++) {
                const ull* wp = (const ull*)(w2base + i * W2STRIDE);
                ull w0 = wp[0], w1 = wp[1], w2 = wp[2], w3 = wp[3];
                float v0 = vr0[i], v1 = vr1[i], v2 = vr2[i], v3 = vr3[i];
                ull vv0 = pk2(v0, v0), vv1 = pk2(v1, v1);
                ull vv2 = pk2(v2, v2), vv3 = pk2(v3, v3);
                a[0][0] = fma2(vv0, w0, a[0][0]); a[0][1] = fma2(vv0, w1, a[0][1]);
                a[0][2] = fma2(vv0, w2, a[0][2]); a[0][3] = fma2(vv0, w3, a[0][3]);
                a[1][0] = fma2(vv1, w0, a[1][0]); a[1][1] = fma2(vv1, w1, a[1][1]);
                a[1][2] = fma2(vv1, w2, a[1][2]); a[1][3] = fma2(vv1, w3, a[1][3]);
                a[2][0] = fma2(vv2, w0, a[2][0]); a[2][1] = fma2(vv2, w1, a[2][1]);
                a[2][2] = fma2(vv2, w2, a[2][2]); a[2][3] = fma2(vv2, w3, a[2][3]);
                a[3][0] = fma2(vv3, w0, a[3][0]); a[3][1] = fma2(vv3, w1, a[3][1]);
                a[3][2] = fma2(vv3, w2, a[3][2]); a[3][3] = fma2(vv3, w3, a[3][3]);
            }
            #pragma unroll
            for (int r = 0; r < 4; r++) {
                ulonglong2 q0, q1;
                q0.x = a[r][0]; q0.y = a[r][1]; q1.x = a[r][2]; q1.y = a[r][3];
                ((ulonglong2*)(gp + r * FN))[0] = q0;
                ((ulonglong2*)(gp + r * FN))[1] = q1;
            }
        }
    }
    __syncthreads();
}

__device__ void panel_factor(float* Vp, float* taus, float* betas, float* sred,
                             float* wred, float* scal, int o, int tid)
{
    const int lane = tid & 31, w = tid >> 5;
    for (int i = 0; i < NB; i++) {
        const int prow = o + i;
        float val = 0.f;
        if (tid >= prow) val = VP(tid, i);
        if (tid == prow) scal[0] = val;
        float sq = (tid > prow) ? val * val : 0.f;
        sq = wsum(sq);
        if (lane == 0) sred[w] = sq;
        __syncthreads();
        if (tid == 0) {
            float s2 = 0.f;
            #pragma unroll
            for (int k = 0; k < 16; k++) s2 += sred[k];
            float alpha = scal[0], tau, sc, beta;
            if (s2 == 0.f) {
                tau = 0.f; sc = 0.f; beta = alpha;
            } else {
                beta = -copysignf(sqrtf(alpha * alpha + s2), alpha);
                tau = (beta - alpha) / beta;
                sc = 1.f / (alpha - beta);
            }
            scal[1] = tau; scal[2] = sc;
            taus[i] = tau; betas[i] = beta;
        }
        __syncthreads();
        const float tau = scal[1], sc = scal[2];
        if (tid > prow)       VP(tid, i) = val * sc;
        else if (tid == prow) VP(tid, i) = 1.f;
        __syncthreads();
        if (tau != 0.f && i < NB - 1) {
            const int c0 = w, c1 = w + 16;
            float p0 = 0.f, p1 = 0.f;
            for (int t = prow + lane; t < TN; t += 32) {
                float vi = VP(t, i);
                p0 += vi * VP(t, c0);
                p1 += vi * VP(t, c1);
            }
            p0 = wsum(p0); p1 = wsum(p1);
            if (lane == 0) { wred[c0] = p0; wred[c1] = p1; }
            __syncthreads();
            float tw = tau * wred[lane];
            if (lane > i) {
                for (int t = prow + w; t < TN; t += 16)
                    VP(t, lane) -= tw * VP(t, i);
            }
            __syncthreads();
        }
    }
}

__device__ void build_T(const float* Vp, float* B, float* Tp, const float* taus,
                        int o, int tid)
{
    const int lane = tid & 31, w = tid >> 5;
    for (int i = 1; i < NB; i++) {
        for (int j = w; j < i; j += 16) {
            float p = 0.f;
            for (int t = o + i + lane; t < TN; t += 32)
                p += VP(t, j) * VP(t, i);
            p = wsum(p);
            if (lane == 0) B[j * 32 + i] = p;
        }
    }
    __syncthreads();
    if (w == 0) {
        for (int i = 0; i < NB; i++) {
            float ti = taus[i];
            float a = 0.f;
            for (int k = 0; k < i; k++)
                a += Tp[lane * 33 + k] * B[k * 32 + i];
            float tv = (lane < i) ? -ti * a : (lane == i ? ti : 0.f);
            Tp[lane * 33 + i] = tv;
            __syncwarp();
        }
    }
    __syncthreads();
}

// SMEM (floats): Vp 16896 | Tp 1056 | Wm 3072 | Wm2 3840 | taus 32 | betas 32 | sred 16 | wred 32 | scal 4
#define SM_FLOATS (16896 + 1056 + 3072 + 3840 + 32 + 32 + 16 + 32 + 4)
#define SM_BYTES  (SM_FLOATS * 4)

__global__ __launch_bounds__(512, 2) void qr_kernel()
{
    extern __shared__ float sm[];
    float* Vp    = sm;                 // 16896
    float* Tp    = Vp + 16896;         // 1056
    float* Wm    = Tp + 1056;          // 3072
    float* Wm2   = Wm + 3072;          // 3840 (also GEMM1 staging + build_T B)
    float* taus  = Wm2 + 3840;         // 32
    float* betas = taus + 32;          // 32
    float* sred  = betas + 32;         // 16
    float* wred  = sred + 16;          // 32
    float* scal  = wred + 32;          // 4

    const int b = blockIdx.x;
    float* G = g_scratch + (size_t)b * TN * FN;
    const int tid = threadIdx.x;
    const int lane = tid & 31, w = tid >> 5;

    // ---------------- geqrf (blocked, trailing only) ----------------
    for (int p = 0; p < 4; p++) {
        const int o = p * 32;
        for (int t = o + w; t < TN; t += 16)
            VP(t, lane) = G[(size_t)t * FN + o + lane];
        __syncthreads();
        panel_factor(Vp, taus, betas, sred, wred, scal, o, tid);
        // write the 32x32 R block of this panel to scratch (zeros below diag)
        for (int pos = tid; pos < 32 * 32; pos += 512) {
            int r = pos >> 5, i = pos & 31;
            float val = (r < i) ? VP(o + r, i) : (r == i ? betas[i] : 0.f);
            G[(size_t)(o + r) * FN + o + i] = val;
        }
        __syncthreads();
        if (p < 3) {
            // zero junk above panel diagonal (V must be unit-lower)
            for (int pos = tid; pos < 32 * 32; pos += 512) {
                int i = pos >> 5, r = pos & 31;
                if (r < i) VP(o + r, i) = 0.f;
            }
            __syncthreads();
            build_T(Vp, Wm2, Tp, taus, o, tid);
            if (p == 0)      block_apply<96>(G, 0,  32, Vp, Tp, Wm, Wm2, tid);
            else if (p == 1) block_apply<64>(G, 32, 64, Vp, Tp, Wm, Wm2, tid);
            else             block_apply<32>(G, 64, 96, Vp, Tp, Wm, Wm2, tid);
        }
    }
    __syncthreads();

    // ---------------- R^{-1} (upper-triangular inverse) ----------------
    float* Rsm = sm;             // 128 x 130 = 16640 (overlays Vp)
    float* rd  = sm + 16640;     // 128 reciprocals
    for (int e = tid; e < 128 * 128; e += 512) {
        int r = e >> 7, c = e & 127;
        Rsm[r * 130 + c] = G[(size_t)r * FN + c];
    }
    __syncthreads();
    if (tid < 128) rd[tid] = 1.f / Rsm[tid * 130 + tid];
    __syncthreads();

    // warp w solves columns c = w + 16*m  (m = 0..7)
    for (int m = 0; m < 8; m++) {
        int c = w + (m << 4);
        float x0 = 0.f, x1 = 0.f, x2 = 0.f, x3 = 0.f;
        {
            float xc = rd[c];
            int q = c >> 5;
            if ((c & 31) == lane) {
                if (q == 0) x0 = xc; else if (q == 1) x1 = xc;
                else if (q == 2) x2 = xc; else x3 = xc;
            }
        }
        const int m0 = lane, m1 = lane + 32, m2 = lane + 64, m3 = lane + 96;
        for (int k = c - 1; k >= 0; k--) {
            const float* Rk = Rsm + k * 130;
            float rk = rd[k];
            float s = 0.f;
            if (m0 > k && m0 <= c) s += Rk[m0] * x0;
            if (m1 > k && m1 <= c) s += Rk[m1] * x1;
            if (m2 > k && m2 <= c) s += Rk[m2] * x2;
            if (m3 > k && m3 <= c) s += Rk[m3] * x3;
            s = wsum(s);
            float xk = -s * rk;
            if ((k & 31) == lane) {
                int q = k >> 5;
                if (q == 0) x0 = xk; else if (q == 1) x1 = xk;
                else if (q == 2) x2 = xk; else x3 = xk;
            }
        }
        // write dense Rinv column c (zeros below diagonal)
        G[(size_t)m0 * FN + c] = (m0 <= c) ? x0 : 0.f;
        G[(size_t)m1 * FN + c] = (m1 <= c) ? x1 : 0.f;
        G[(size_t)m2 * FN + c] = (m2 <= c) ? x2 : 0.f;
        G[(size_t)m3 * FN + c] = (m3 <= c) ? x3 : 0.f;
    }
}

// ============================================================
// TRSM-GEMM: Q = Y * Rinv.  One CTA per 32-row tile (4096 CTAs).
// Rinv staged group-10-padded [k][160]; Y staged transposed [k][33].
// ============================================================
#define TRSM_SM ((128 * 160 + 128 * 33) * 4)

__global__ __launch_bounds__(256, 2) void trsm_kernel(float* __restrict__ Yq)
{
    extern __shared__ float s[];
    float* Rg = s;              // 128 x 160 (groups of 8 cols padded to 10)
    float* Ys = s + 128 * 160;  // 128 x 33  ([k][r])

    const int cta  = blockIdx.x;
    const int bidx = cta >> 4;
    const int tile = cta & 15;
    const int tid  = threadIdx.x;
    float* Y = Yq + (size_t)bidx * TN * FN + (size_t)tile * 32 * FN;
    const float* Ri = g_scratch + (size_t)bidx * TN * FN;

    // stage Rinv (128x128) into padded layout
    #pragma unroll
    for (int e = tid; e < 128 * 32; e += 256) {
        int k = e >> 5, g4 = e & 31;
        float4 v = *(const float4*)(Ri + (size_t)k * FN + g4 * 4);
        int cg = g4 >> 1, off = (g4 & 1) * 4;
        float* dst = Rg + k * 160 + cg * 10 + off;
        dst[0] = v.x; dst[1] = v.y; dst[2] = v.z; dst[3] = v.w;
    }
    // stage Y tile transposed
    #pragma unroll
    for (int e = tid; e < 32 * 32; e += 256) {
        int r = e >> 5, g4 = e & 31;
        float4 v = *(const float4*)(Y + (size_t)r * FN + g4 * 4);
        float* dst = Ys + (g4 * 4) * 33 + r;
        dst[0] = v.x; dst[33] = v.y; dst[66] = v.z; dst[99] = v.w;
    }
    __syncthreads();

    const int w = tid >> 5, lane = tid & 31;
    const int cb   = (w < 4) ? w : 7 - w;       // col block, SMSP-balanced
    const int half = w >> 2;
    const int rg   = lane & 15;
    const int cgi  = (lane >> 4) | (half << 1);
    const int r0   = rg * 2;
    const int c0   = cb * 32 + cgi * 8;
    const int kmax = (cb + 1) * 32;

    ull a0[4], a1[4];
    #pragma unroll
    for (int q = 0; q < 4; q++) { a0[q] = 0ull; a1[q] = 0ull; }

    const float* wbase = Rg + (size_t)(cb * 4 + cgi) * 10;
    const float* ybase = Ys + r0;
    #pragma unroll 4
    for (int k = 0; k < kmax; k++) {
        float y0 = ybase[k * 33];
        float y1 = ybase[k * 33 + 1];
        ull v0 = pk2(y0, y0), v1 = pk2(y1, y1);
        const ull* wp = (const ull*)(wbase + k * 160);
        ull w0 = wp[0], w1 = wp[1], w2 = wp[2], w3 = wp[3];
        a0[0] = fma2(v0, w0, a0[0]); a0[1] = fma2(v0, w1, a0[1]);
        a0[2] = fma2(v0, w2, a0[2]); a0[3] = fma2(v0, w3, a0[3]);
        a1[0] = fma2(v1, w0, a1[0]); a1[1] = fma2(v1, w1, a1[1]);
        a1[2] = fma2(v1, w2, a1[2]); a1[3] = fma2(v1, w3, a1[3]);
    }

    float* out0 = Y + (size_t)r0 * FN + c0;
    float* out1 = out0 + FN;
    ulonglong2 q0, q1;
    q0.x = a0[0]; q0.y = a0[1]; q1.x = a0[2]; q1.y = a0[3];
    ((ulonglong2*)out0)[0] = q0; ((ulonglong2*)out0)[1] = q1;
    q0.x = a1[0]; q0.y = a1[1]; q1.x = a1[2]; q1.y = a1[3];
    ((ulonglong2*)out1)[0] = q0; ((ulonglong2*)out1)[1] = q1;
}

// ============================================================
extern "C" void kernel_launch(void* const* d_in, const int* in_sizes, int n_in,
                              void* d_out, int out_size)
{
    const float* x    = (const float*)d_in[0];
    const float* W    = (const float*)d_in[1];
    const float* bias = (const float*)d_in[2];
    float* out = (float*)d_out;

    cudaFuncSetAttribute(qr_kernel, cudaFuncAttributeMaxDynamicSharedMemorySize, SM_BYTES);
    cudaFuncSetAttribute(trsm_kernel, cudaFuncAttributeMaxDynamicSharedMemorySize, TRSM_SM);

    dim3 cgrid(TN / 64, BN);
    conv_kernel<<<cgrid, 256>>>(x, W, bias, out);   // Y -> d_out AND scratch
    qr_kernel<<<BN, 512, SM_BYTES>>>();             // geqrf + Rinv on scratch
    trsm_kernel<<<BN * 16, 256, TRSM_SM>>>(out);    // Q = Y * Rinv, in-place
}

// round 9
// speedup vs baseline: 1.1069x; 1.1069x over previous
#include <cuda_runtime.h>

#define BN 256
#define TN 512
#define CN 128
#define FN 128
#define NB 32

typedef unsigned long long ull;

__device__ float g_scratch[(size_t)BN * TN * FN];   // 64 MB scratch

__device__ __forceinline__ ull pk2(float lo, float hi) {
    ull r; asm("mov.b64 %0, {%1, %2};" : "=l"(r) : "f"(lo), "f"(hi)); return r;
}
__device__ __forceinline__ void upk2(ull v, float& lo, float& hi) {
    asm("mov.b64 {%0, %1}, %2;" : "=f"(lo), "=f"(hi) : "l"(v));
}
__device__ __forceinline__ ull fma2(ull a, ull b, ull c) {
    ull d; asm("fma.rn.f32x2 %0, %1, %2, %3;" : "=l"(d) : "l"(a), "l"(b), "l"(c)); return d;
}
__device__ __forceinline__ float wsum(float v) {
    #pragma unroll
    for (int o = 16; o; o >>= 1) v += __shfl_xor_sync(0xffffffffu, v, o);
    return v;
}

// ============================================================
// Conv1D: writes y to BOTH d_out (preserved Y) and scratch (destroyed by geqrf)
// ============================================================
__global__ __launch_bounds__(256) void conv_kernel(
    const float* __restrict__ x, const float* __restrict__ W,
    const float* __restrict__ bias, float* __restrict__ y)
{
    __shared__ float Xs[64][33];
    __shared__ float Ws[32][128];

    const int b = blockIdx.y, t0 = blockIdx.x * 64, tid = threadIdx.x;
    const int lane = tid & 31, warp = tid >> 5;
    const int cbase = lane * 4, rbase = warp * 8;

    ull acc2[8][2];
    #pragma unroll
    for (int i = 0; i < 8; i++) { acc2[i][0] = 0ull; acc2[i][1] = 0ull; }

    for (int k = 0; k < 3; k++) {
        for (int c0 = 0; c0 < CN; c0 += 32) {
            #pragma unroll
            for (int q = 0; q < 16; q++) {
                int e = tid + 256 * q, f = e & 127, cc = e >> 7;
                Ws[cc][f] = W[((size_t)(k * CN + c0 + cc)) * FN + f];
            }
            #pragma unroll
            for (int q = 0; q < 8; q++) {
                int e = tid + 256 * q, cc = e & 31, r = e >> 5;
                int t = t0 + r + k - 1;
                float v = 0.f;
                if (t >= 0 && t < TN) v = x[((size_t)b * TN + t) * CN + c0 + cc];
                Xs[r][cc] = v;
            }
            __syncthreads();
            #pragma unroll
            for (int cc = 0; cc < 32; cc++) {
                const ull* wp = (const ull*)&Ws[cc][cbase];
                ull w01 = wp[0], w23 = wp[1];
                #pragma unroll
                for (int i = 0; i < 8; i++) {
                    float xv = Xs[rbase + i][cc];
                    ull xx = pk2(xv, xv);
                    acc2[i][0] = fma2(xx, w01, acc2[i][0]);
                    acc2[i][1] = fma2(xx, w23, acc2[i][1]);
                }
            }
            __syncthreads();
        }
    }
    float b0 = bias[cbase], b1 = bias[cbase+1], b2 = bias[cbase+2], b3 = bias[cbase+3];
    #pragma unroll
    for (int i = 0; i < 8; i++) {
        int t = t0 + rbase + i;
        float4 o; float lo, hi;
        upk2(acc2[i][0], lo, hi); o.x = lo + b0; o.y = hi + b1;
        upk2(acc2[i][1], lo, hi); o.z = lo + b2; o.w = hi + b3;
        size_t off = ((size_t)b * TN + t) * FN + cbase;
        *(float4*)&y[off] = o;
        *(float4*)&g_scratch[off] = o;
    }
}

// ============================================================
// geqrf (blocked WY) + blocked-ILP R^{-1}, one CTA per matrix.
// ============================================================
#define VP(t,i)   Vp[(t) * 33 + (i)]
#define W2STRIDE  120

template<int WT>
__device__ void block_apply(float* __restrict__ G, int o, int colbase,
                            const float* __restrict__ Vp, const float* __restrict__ Tp,
                            float* __restrict__ Wm, float* __restrict__ Wm2, int tid)
{
    const int lane = tid & 31, w = tid >> 5;
    constexpr int NU = WT / 32;
    constexpr int HW = WT / 2;
    constexpr int TU = 32 * HW;
    ull* Gs = (ull*)Wm2;

    // GEMM1: Wm[i][c] = sum_t V[t][i]*G[t][colbase+c]
    ull acc[NU];
    #pragma unroll
    for (int k = 0; k < NU; k++) acc[k] = 0ull;
    const int ntiles = (TN - o) >> 5;
    for (int tile = 0; tile < ntiles; tile++) {
        const int t0 = o + (tile << 5);
        #pragma unroll
        for (int u = tid; u < TU; u += 512) {
            int r = u / HW, c = u - r * HW;
            Gs[u] = *(const ull*)(G + (size_t)(t0 + r) * FN + colbase + 2 * c);
        }
        __syncthreads();
        #pragma unroll
        for (int r = 0; r < 32; r++) {
            float v = VP(t0 + r, lane);
            ull vv = pk2(v, v);
            const ull* g = Gs + r * HW + w * NU;
            #pragma unroll
            for (int k = 0; k < NU; k++) acc[k] = fma2(vv, g[k], acc[k]);
        }
        __syncthreads();
    }
    {
        ull* wout = (ull*)(Wm + lane * 96) + w * NU;
        #pragma unroll
        for (int k = 0; k < NU; k++) wout[k] = acc[k];
    }
    __syncthreads();

    // Tapply: Wm2 = -(T^T * Wm), group-10 padded
    {
        constexpr int NCG = WT / 8;
        for (int pos = tid; pos < 32 * NCG * 4; pos += 512) {
            int i = pos / (NCG * 4);
            int rem = pos - i * (NCG * 4);
            int cg = rem >> 2, k = rem & 3;
            int c = cg * 8 + 2 * k;
            ull a = 0ull;
            #pragma unroll
            for (int j = 0; j < 32; j++) {
                float tv = Tp[j * 33 + i];
                a = fma2(pk2(-tv, -tv), *(const ull*)(Wm + j * 96 + c), a);
            }
            *(ull*)(Wm2 + i * W2STRIDE + cg * 10 + 2 * k) = a;
        }
    }
    __syncthreads();

    // GEMM2: G += V * Wm2
    {
        constexpr int NCG = WT / 8;
        const int npos = ((TN - o) >> 2) * NCG;
        for (int pos = tid; pos < npos; pos += 512) {
            int tg = pos / NCG, cg = pos - tg * NCG;
            int t0 = o + (tg << 2);
            float* gp = G + (size_t)t0 * FN + colbase + cg * 8;
            ull a[4][4];
            #pragma unroll
            for (int r = 0; r < 4; r++) {
                ulonglong2 q0 = ((const ulonglong2*)(gp + r * FN))[0];
                ulonglong2 q1 = ((const ulonglong2*)(gp + r * FN))[1];
                a[r][0] = q0.x; a[r][1] = q0.y; a[r][2] = q1.x; a[r][3] = q1.y;
            }
            const float* vr0 = Vp + (size_t)t0 * 33;
            const float* vr1 = vr0 + 33;
            const float* vr2 = vr1 + 33;
            const float* vr3 = vr2 + 33;
            const float* w2base = Wm2 + cg * 10;
            #pragma unroll 4
            for (int i = 0; i < 32; i++) {
                const ull* wp = (const ull*)(w2base + i * W2STRIDE);
                ull w0 = wp[0], w1 = wp[1], w2 = wp[2], w3 = wp[3];
                float v0 = vr0[i], v1 = vr1[i], v2 = vr2[i], v3 = vr3[i];
                ull vv0 = pk2(v0, v0), vv1 = pk2(v1, v1);
                ull vv2 = pk2(v2, v2), vv3 = pk2(v3, v3);
                a[0][0] = fma2(vv0, w0, a[0][0]); a[0][1] = fma2(vv0, w1, a[0][1]);
                a[0][2] = fma2(vv0, w2, a[0][2]); a[0][3] = fma2(vv0, w3, a[0][3]);
                a[1][0] = fma2(vv1, w0, a[1][0]); a[1][1] = fma2(vv1, w1, a[1][1]);
                a[1][2] = fma2(vv1, w2, a[1][2]); a[1][3] = fma2(vv1, w3, a[1][3]);
                a[2][0] = fma2(vv2, w0, a[2][0]); a[2][1] = fma2(vv2, w1, a[2][1]);
                a[2][2] = fma2(vv2, w2, a[2][2]); a[2][3] = fma2(vv2, w3, a[2][3]);
                a[3][0] = fma2(vv3, w0, a[3][0]); a[3][1] = fma2(vv3, w1, a[3][1]);
                a[3][2] = fma2(vv3, w2, a[3][2]); a[3][3] = fma2(vv3, w3, a[3][3]);
            }
            #pragma unroll
            for (int r = 0; r < 4; r++) {
                ulonglong2 q0, q1;
                q0.x = a[r][0]; q0.y = a[r][1]; q1.x = a[r][2]; q1.y = a[r][3];
                ((ulonglong2*)(gp + r * FN))[0] = q0;
                ((ulonglong2*)(gp + r * FN))[1] = q1;
            }
        }
    }
    __syncthreads();
}

// Fused panel factorization: 2 barriers + 1 reduction chain per column.
__device__ void panel_factor(float* Vp, float* taus, float* betas,
                             float* wred, float* rowp, int o, int tid)
{
    const int lane = tid & 31, w = tid >> 5;
    const int c0 = w, c1 = w + 16;
    for (int i = 0; i < NB; i++) {
        const int prow = o + i;
        // snapshot row prow (stable since last barrier)
        if (w == 0) rowp[lane] = VP(prow, lane);
        // Phase A: s_j = sum_{t>=prow} x_t * c_j[t]  (j = c0, c1; j=i gives norm^2)
        float p0 = 0.f, p1 = 0.f;
        for (int t = prow + lane; t < TN; t += 32) {
            float vi = VP(t, i);
            p0 += vi * VP(t, c0);
            p1 += vi * VP(t, c1);
        }
        p0 = wsum(p0); p1 = wsum(p1);
        if (lane == 0) { wred[c0] = p0; wred[c1] = p1; }
        __syncthreads();
        // redundant scalar compute (all threads; cheaper than a barrier)
        float alpha = rowp[i];
        float s2 = wred[i];
        float xn2 = s2 - alpha * alpha;
        float tau, sc, beta;
        if (xn2 <= 0.f) { tau = 0.f; sc = 0.f; beta = alpha; }
        else {
            beta = -copysignf(sqrtf(s2), alpha);
            tau  = (beta - alpha) / beta;
            sc   = 1.f / (alpha - beta);
        }
        if (tid == 0) { taus[i] = tau; betas[i] = beta; }
        // per-column coefficient (lane = column j)
        float cjp  = rowp[lane];
        float coef = tau * (cjp + (wred[lane] - alpha * cjp) * sc);
        // Phase C: fused rank-1 update (j>i) + scale column i into v
        if (w == 0) {
            float nv = (lane == i) ? 1.f : cjp - coef;
            if (lane >= i) VP(prow, lane) = nv;
        }
        for (int t = prow + 1 + w; t < TN; t += 16) {
            float xt  = VP(t, i);          // broadcast (pre-update x)
            float vt  = xt * sc;
            float cur = VP(t, lane);
            float nv  = (lane == i) ? vt : fmaf(-coef, vt, cur);
            if (lane >= i) VP(t, lane) = nv;
        }
        __syncthreads();
    }
}

__device__ void build_T(const float* Vp, float* B, float* Tp, const float* taus,
                        int o, int tid)
{
    const int lane = tid & 31, w = tid >> 5;
    for (int i = 1; i < NB; i++) {
        for (int j = w; j < i; j += 16) {
            float p = 0.f;
            for (int t = o + i + lane; t < TN; t += 32)
                p += VP(t, j) * VP(t, i);
            p = wsum(p);
            if (lane == 0) B[j * 32 + i] = p;
        }
    }
    __syncthreads();
    if (w == 0) {
        for (int i = 0; i < NB; i++) {
            float ti = taus[i];
            float a = 0.f;
            for (int k = 0; k < i; k++)
                a += Tp[lane * 33 + k] * B[k * 32 + i];
            float tv = (lane < i) ? -ti * a : (lane == i ? ti : 0.f);
            Tp[lane * 33 + i] = tv;
            __syncwarp();
        }
    }
    __syncthreads();
}

// SMEM (floats): Vp 16896 | Tp 1056 | Wm 3072 | Wm2 3840 | taus 32 | betas 32 | wred 32 | rowp 32
#define SM_FLOATS (16896 + 1056 + 3072 + 3840 + 32 + 32 + 32 + 32)
#define SM_BYTES  (SM_FLOATS * 4)

__global__ __launch_bounds__(512, 2) void qr_kernel()
{
    extern __shared__ float sm[];
    float* Vp    = sm;                 // 16896
    float* Tp    = Vp + 16896;         // 1056
    float* Wm    = Tp + 1056;          // 3072
    float* Wm2   = Wm + 3072;          // 3840 (also GEMM1 staging + build_T B)
    float* taus  = Wm2 + 3840;         // 32
    float* betas = taus + 32;          // 32
    float* wred  = betas + 32;         // 32
    float* rowp  = wred + 32;          // 32

    const int b = blockIdx.x;
    float* G = g_scratch + (size_t)b * TN * FN;
    const int tid = threadIdx.x;
    const int lane = tid & 31, w = tid >> 5;

    // ---------------- geqrf (blocked, trailing only) ----------------
    for (int p = 0; p < 4; p++) {
        const int o = p * 32;
        for (int t = o + w; t < TN; t += 16)
            VP(t, lane) = G[(size_t)t * FN + o + lane];
        __syncthreads();
        panel_factor(Vp, taus, betas, wred, rowp, o, tid);
        // write the 32x32 R block of this panel (zeros below diag)
        for (int pos = tid; pos < 32 * 32; pos += 512) {
            int r = pos >> 5, i = pos & 31;
            float val = (r < i) ? VP(o + r, i) : (r == i ? betas[i] : 0.f);
            G[(size_t)(o + r) * FN + o + i] = val;
        }
        __syncthreads();
        if (p < 3) {
            // zero junk above panel diagonal (V must be unit-lower)
            for (int pos = tid; pos < 32 * 32; pos += 512) {
                int i = pos >> 5, r = pos & 31;
                if (r < i) VP(o + r, i) = 0.f;
            }
            __syncthreads();
            build_T(Vp, Wm2, Tp, taus, o, tid);
            if (p == 0)      block_apply<96>(G, 0,  32, Vp, Tp, Wm, Wm2, tid);
            else if (p == 1) block_apply<64>(G, 32, 64, Vp, Tp, Wm, Wm2, tid);
            else             block_apply<32>(G, 64, 96, Vp, Tp, Wm, Wm2, tid);
        }
    }
    __syncthreads();

    // ---------------- R^{-1} with 8-column ILP per warp ----------------
    float* Rsm = sm;             // 128 x 130 (overlays Vp)
    float* rd  = sm + 16640;     // 128 reciprocals
    for (int e = tid; e < 128 * 128; e += 512) {
        int r = e >> 7, c = e & 127;
        Rsm[r * 130 + c] = G[(size_t)r * FN + c];
    }
    __syncthreads();
    if (tid < 128) rd[tid] = 1.f / Rsm[tid * 130 + tid];
    __syncthreads();

    // warp w owns columns C[m] = w + 16m; solve all 8 concurrently
    float xr[8][4];
    #pragma unroll
    for (int m = 0; m < 8; m++) {
        #pragma unroll
        for (int q = 0; q < 4; q++) xr[m][q] = 0.f;
        int c = w + (m << 4);
        float dv = rd[c];
        if ((c & 31) == lane) {
            int q = c >> 5;
            if (q == 0) xr[m][0] = dv; else if (q == 1) xr[m][1] = dv;
            else if (q == 2) xr[m][2] = dv; else xr[m][3] = dv;
        }
    }
    for (int k = 126; k >= 0; k--) {
        const float* Rk = Rsm + k * 130;
        float r0 = Rk[lane], r1 = Rk[lane + 32], r2 = Rk[lane + 64], r3 = Rk[lane + 96];
        float rk = rd[k];
        int qk = k >> 5, lk = k & 31;
        #pragma unroll
        for (int m = 0; m < 8; m++) {
            int c = w + (m << 4);
            if (c > k) {    // warp-uniform branch
                float s = r0 * xr[m][0] + r1 * xr[m][1] + r2 * xr[m][2] + r3 * xr[m][3];
                s = wsum(s);
                float xk = -s * rk;
                if (lk == lane) {
                    if (qk == 0) xr[m][0] = xk; else if (qk == 1) xr[m][1] = xk;
                    else if (qk == 2) xr[m][2] = xk; else xr[m][3] = xk;
                }
            }
        }
    }
    // write dense Rinv (zeros below diagonal) back to scratch rows 0..127
    #pragma unroll
    for (int m = 0; m < 8; m++) {
        int c = w + (m << 4);
        G[(size_t)lane * FN + c]        = (lane <= c)      ? xr[m][0] : 0.f;
        G[(size_t)(lane + 32) * FN + c] = (lane + 32 <= c) ? xr[m][1] : 0.f;
        G[(size_t)(lane + 64) * FN + c] = (lane + 64 <= c) ? xr[m][2] : 0.f;
        G[(size_t)(lane + 96) * FN + c] = (lane + 96 <= c) ? xr[m][3] : 0.f;
    }
}

// ============================================================
// TRSM-GEMM: Q = Y * Rinv.  One CTA per 32-row tile (4096 CTAs).
// ============================================================
#define TRSM_SM ((128 * 160 + 128 * 33) * 4)

__global__ __launch_bounds__(256, 2) void trsm_kernel(float* __restrict__ Yq)
{
    extern __shared__ float s[];
    float* Rg = s;              // 128 x 160 (groups of 8 cols padded to 10)
    float* Ys = s + 128 * 160;  // 128 x 33  ([k][r])

    const int cta  = blockIdx.x;
    const int bidx = cta >> 4;
    const int tile = cta & 15;
    const int tid  = threadIdx.x;
    float* Y = Yq + (size_t)bidx * TN * FN + (size_t)tile * 32 * FN;
    const float* Ri = g_scratch + (size_t)bidx * TN * FN;

    #pragma unroll
    for (int e = tid; e < 128 * 32; e += 256) {
        int k = e >> 5, g4 = e & 31;
        float4 v = *(const float4*)(Ri + (size_t)k * FN + g4 * 4);
        int cg = g4 >> 1, off = (g4 & 1) * 4;
        float* dst = Rg + k * 160 + cg * 10 + off;
        dst[0] = v.x; dst[1] = v.y; dst[2] = v.z; dst[3] = v.w;
    }
    #pragma unroll
    for (int e = tid; e < 32 * 32; e += 256) {
        int r = e >> 5, g4 = e & 31;
        float4 v = *(const float4*)(Y + (size_t)r * FN + g4 * 4);
        float* dst = Ys + (g4 * 4) * 33 + r;
        dst[0] = v.x; dst[33] = v.y; dst[66] = v.z; dst[99] = v.w;
    }
    __syncthreads();

    const int w = tid >> 5, lane = tid & 31;
    const int cb   = (w < 4) ? w : 7 - w;       // col block, SMSP-balanced
    const int half = w >> 2;
    const int rg   = lane & 15;
    const int cgi  = (lane >> 4) | (half << 1);
    const int r0   = rg * 2;
    const int c0   = cb * 32 + cgi * 8;
    const int kmax = (cb + 1) * 32;

    ull a0[4], a1[4];
    #pragma unroll
    for (int q = 0; q < 4; q++) { a0[q] = 0ull; a1[q] = 0ull; }

    const float* wbase = Rg + (size_t)(cb * 4 + cgi) * 10;
    const float* ybase = Ys + r0;
    #pragma unroll 4
    for (int k = 0; k < kmax; k++) {
        float y0 = ybase[k * 33];
        float y1 = ybase[k * 33 + 1];
        ull v0 = pk2(y0, y0), v1 = pk2(y1, y1);
        const ull* wp = (const ull*)(wbase + k * 160);
        ull w0 = wp[0], w1 = wp[1], w2 = wp[2], w3 = wp[3];
        a0[0] = fma2(v0, w0, a0[0]); a0[1] = fma2(v0, w1, a0[1]);
        a0[2] = fma2(v0, w2, a0[2]); a0[3] = fma2(v0, w3, a0[3]);
        a1[0] = fma2(v1, w0, a1[0]); a1[1] = fma2(v1, w1, a1[1]);
        a1[2] = fma2(v1, w2, a1[2]); a1[3] = fma2(v1, w3, a1[3]);
    }

    float* out0 = Y + (size_t)r0 * FN + c0;
    float* out1 = out0 + FN;
    ulonglong2 q0, q1;
    q0.x = a0[0]; q0.y = a0[1]; q1.x = a0[2]; q1.y = a0[3];
    ((ulonglong2*)out0)[0] = q0; ((ulonglong2*)out0)[1] = q1;
    q0.x = a1[0]; q0.y = a1[1]; q1.x = a1[2]; q1.y = a1[3];
    ((ulonglong2*)out1)[0] = q0; ((ulonglong2*)out1)[1] = q1;
}

// ============================================================
extern "C" void kernel_launch(void* const* d_in, const int* in_sizes, int n_in,
                              void* d_out, int out_size)
{
    const float* x    = (const float*)d_in[0];
    const float* W    = (const float*)d_in[1];
    const float* bias = (const float*)d_in[2];
    float* out = (float*)d_out;

    cudaFuncSetAttribute(qr_kernel, cudaFuncAttributeMaxDynamicSharedMemorySize, SM_BYTES);
    cudaFuncSetAttribute(trsm_kernel, cudaFuncAttributeMaxDynamicSharedMemorySize, TRSM_SM);

    dim3 cgrid(TN / 64, BN);
    conv_kernel<<<cgrid, 256>>>(x, W, bias, out);   // Y -> d_out AND scratch
    qr_kernel<<<BN, 512, SM_BYTES>>>();             // geqrf + Rinv on scratch
    trsm_kernel<<<BN * 16, 256, TRSM_SM>>>(out);    // Q = Y * Rinv, in-place
}